// round 15
// baseline (speedup 1.0000x reference)
#include <cuda_runtime.h>

// TAHE: masked cosine-similarity weighted pooling, fused single-pass.
// 16-lane row groups: half-warp owns a row (lane holds 8 elems = 2 coalesced float4),
// 4-level butterfly reduces TWO rows per SHFL instruction (4 SHFL/row vs 10).
// x2 unroll per group (4 rows/warp-iter) keeps 8 LDG.128 in flight.
// Shuffles unconditional (offsets <=8 never cross the 16-lane group); loads predicated
// by the mask so ~50% of DRAM rows are skipped.
// out[b,d] = sum_l [ts[b,l]>0] * (cos(cur_n[b], rec[b,l]) + 1)/2 * items[b,l,d]
// B=4096, L=200, D=128 f32.

#define TB 4096
#define TL 200
#define TD 128
#define WARPS 8
#define TEPS 1e-12f

__global__ __launch_bounds__(WARPS * 32, 1)
void tahe_kernel(const float* __restrict__ rec,
                 const float* __restrict__ cur,
                 const int*   __restrict__ ts,
                 const float* __restrict__ items,
                 float*       __restrict__ out)
{
    const int b      = blockIdx.x;
    const int tid    = threadIdx.x;
    const int wid    = tid >> 5;
    const int lane   = tid & 31;
    const int half   = lane >> 4;      // group id within warp (0/1)
    const int lane16 = lane & 15;

    __shared__ int    tss[TL];
    __shared__ float4 red0[WARPS][32];
    __shared__ float4 red1[WARPS][32];

    // ---- preload mask row into smem ----
    if (tid < TL) tss[tid] = __ldg(&ts[(size_t)b * TL + tid]);

    // ---- normalize cur[b,:] (full warp, redundant per warp) ----
    const float4* cur4 = reinterpret_cast<const float4*>(cur + (size_t)b * TD);
    float4 c = __ldg(&cur4[lane]);
    float ssum = c.x * c.x + c.y * c.y + c.z * c.z + c.w * c.w;
    #pragma unroll
    for (int o = 16; o > 0; o >>= 1)
        ssum += __shfl_xor_sync(0xffffffffu, ssum, o);
    const float rn = rsqrtf(fmaxf(ssum, TEPS));
    c.x *= rn; c.y *= rn; c.z *= rn; c.w *= rn;

    // lane needs normalized cur float4s at indices lane16 and lane16+16
    float4 c0, c1;
    c0.x = __shfl_sync(0xffffffffu, c.x, lane16);
    c0.y = __shfl_sync(0xffffffffu, c.y, lane16);
    c0.z = __shfl_sync(0xffffffffu, c.z, lane16);
    c0.w = __shfl_sync(0xffffffffu, c.w, lane16);
    c1.x = __shfl_sync(0xffffffffu, c.x, lane16 + 16);
    c1.y = __shfl_sync(0xffffffffu, c.y, lane16 + 16);
    c1.z = __shfl_sync(0xffffffffu, c.z, lane16 + 16);
    c1.w = __shfl_sync(0xffffffffu, c.w, lane16 + 16);

    __syncthreads();

    const float4* rec4 = reinterpret_cast<const float4*>(rec   + (size_t)b * TL * TD);
    const float4* it4  = reinterpret_cast<const float4*>(items + (size_t)b * TL * TD);

    // acc0 covers d = lane16*4..+3 ; acc1 covers d = 64 + lane16*4..+3
    float4 acc0 = make_float4(0.f, 0.f, 0.f, 0.f);
    float4 acc1 = make_float4(0.f, 0.f, 0.f, 0.f);

    // ---- mainloop: warp-iter covers rows l0..l0+3; group h owns rows l0+2h, l0+2h+1 ----
    for (int l0 = 4 * wid; l0 < TL; l0 += 4 * WARPS) {
        const int rA = l0 + 2 * half;       // <= 198
        const int rB = rA + 1;              // <= 199
        const int mA = tss[rA];
        const int mB = tss[rB];

        float4 ra0 = make_float4(0.f,0.f,0.f,0.f), ra1 = make_float4(0.f,0.f,0.f,0.f);
        float4 rb0 = make_float4(0.f,0.f,0.f,0.f), rb1 = make_float4(0.f,0.f,0.f,0.f);
        float4 va0 = make_float4(0.f,0.f,0.f,0.f), va1 = make_float4(0.f,0.f,0.f,0.f);
        float4 vb0 = make_float4(0.f,0.f,0.f,0.f), vb1 = make_float4(0.f,0.f,0.f,0.f);

        if (mA > 0) {
            ra0 = __ldg(&rec4[rA * 32 + lane16]);
            ra1 = __ldg(&rec4[rA * 32 + 16 + lane16]);
            va0 = __ldg(&it4 [rA * 32 + lane16]);
            va1 = __ldg(&it4 [rA * 32 + 16 + lane16]);
        }
        if (mB > 0) {
            rb0 = __ldg(&rec4[rB * 32 + lane16]);
            rb1 = __ldg(&rec4[rB * 32 + 16 + lane16]);
            vb0 = __ldg(&it4 [rB * 32 + lane16]);
            vb1 = __ldg(&it4 [rB * 32 + 16 + lane16]);
        }

        float dotA = ra0.x*c0.x + ra0.y*c0.y + ra0.z*c0.z + ra0.w*c0.w
                   + ra1.x*c1.x + ra1.y*c1.y + ra1.z*c1.z + ra1.w*c1.w;
        float sqA  = ra0.x*ra0.x + ra0.y*ra0.y + ra0.z*ra0.z + ra0.w*ra0.w
                   + ra1.x*ra1.x + ra1.y*ra1.y + ra1.z*ra1.z + ra1.w*ra1.w;
        float dotB = rb0.x*c0.x + rb0.y*c0.y + rb0.z*c0.z + rb0.w*c0.w
                   + rb1.x*c1.x + rb1.y*c1.y + rb1.z*c1.z + rb1.w*c1.w;
        float sqB  = rb0.x*rb0.x + rb0.y*rb0.y + rb0.z*rb0.z + rb0.w*rb0.w
                   + rb1.x*rb1.x + rb1.y*rb1.y + rb1.z*rb1.z + rb1.w*rb1.w;

        // 4-level butterfly within 16-lane groups; one instruction reduces both groups.
        // Offsets <= 8 never cross the group boundary -> full-warp unconditional is safe.
        #pragma unroll
        for (int o = 8; o > 0; o >>= 1) {
            dotA += __shfl_xor_sync(0xffffffffu, dotA, o);
            sqA  += __shfl_xor_sync(0xffffffffu, sqA,  o);
            dotB += __shfl_xor_sync(0xffffffffu, dotB, o);
            sqB  += __shfl_xor_sync(0xffffffffu, sqB,  o);
        }

        const float wA = (mA > 0) ? (dotA * rsqrtf(fmaxf(sqA, TEPS)) + 1.0f) * 0.5f : 0.0f;
        const float wB = (mB > 0) ? (dotB * rsqrtf(fmaxf(sqB, TEPS)) + 1.0f) * 0.5f : 0.0f;

        acc0.x += wA * va0.x + wB * vb0.x;
        acc0.y += wA * va0.y + wB * vb0.y;
        acc0.z += wA * va0.z + wB * vb0.z;
        acc0.w += wA * va0.w + wB * vb0.w;
        acc1.x += wA * va1.x + wB * vb1.x;
        acc1.y += wA * va1.y + wB * vb1.y;
        acc1.z += wA * va1.z + wB * vb1.z;
        acc1.w += wA * va1.w + wB * vb1.w;
    }

    // ---- reduce 8 warps x 2 groups per d-slice ----
    red0[wid][lane] = acc0;
    red1[wid][lane] = acc1;
    __syncthreads();

    if (wid == 0) {
        // lane < 16: output float4 index lane   (from acc0 partials, both halves)
        // lane >=16: output float4 index lane   (from acc1 partials at lane16)
        const int j = lane16;
        float4 s = make_float4(0.f, 0.f, 0.f, 0.f);
        if (half == 0) {
            #pragma unroll
            for (int w = 0; w < WARPS; ++w) {
                const float4 a = red0[w][j];
                const float4 bq = red0[w][j + 16];
                s.x += a.x + bq.x; s.y += a.y + bq.y;
                s.z += a.z + bq.z; s.w += a.w + bq.w;
            }
        } else {
            #pragma unroll
            for (int w = 0; w < WARPS; ++w) {
                const float4 a = red1[w][j];
                const float4 bq = red1[w][j + 16];
                s.x += a.x + bq.x; s.y += a.y + bq.y;
                s.z += a.z + bq.z; s.w += a.w + bq.w;
            }
        }
        reinterpret_cast<float4*>(out + (size_t)b * TD)[lane] = s;
    }
}

extern "C" void kernel_launch(void* const* d_in, const int* in_sizes, int n_in,
                              void* d_out, int out_size)
{
    const float* rec   = (const float*)d_in[0]; // recentTimeRepresentations [B,L,D]
    const float* cur   = (const float*)d_in[1]; // curTimeRepresentation    [B,D]
    const int*   ts    = (const int*)  d_in[2]; // recentTimestamps         [B,L]
    const float* items = (const float*)d_in[3]; // recentItemEmbeddings     [B,L,D]
    float*       out   = (float*)d_out;         // [B,D]

    tahe_kernel<<<TB, WARPS * 32>>>(rec, cur, ts, items, out);
}